// round 11
// baseline (speedup 1.0000x reference)
#include <cuda_runtime.h>
#include <cuda_fp16.h>
#include <cstdint>
#include <math.h>

// LSTM B=128, S=256, I=1024, H=1024. out[b,s,h] fp32.
// Phase 1: Xp = x @ Wx^T + bias (fp16 mma m16n8k16, fp32 accum, 128x128 tiles)
// Phase 2: persistent 128-CTA scan, fp16 h/Wh, pair-scoped triple-buffered
//          cp.async pipelines, TWO-LEVEL grid barrier, packed stores.

#define NBLK2 128
#define WS2_STRIDE 516               // 512 + 4 pad (u32) ; row = 1024 fp16
#define AS2_STRIDE 68                // 64 + 4 pad (u32)  ; row = 128 fp16 chunk
#define PAIR_SLAB (3 * 32 * AS2_STRIDE)                 // u32 per pair
#define RED_OFF   (32 * WS2_STRIDE + 4 * PAIR_SLAB)     // u32 offset of reduction area
#define SMEM2_BYTES ((RED_OFF + 128 * 33) * 4)          // 187,392 B

__device__ __align__(16) float    g_Xp[(size_t)256 * 128 * 4096];  // 512 MB
__device__ __align__(16) __half   g_h[2 * 128 * 1024];             // h fp16, dbl buf
__device__ unsigned g_grp[8 * 32];   // 8 group counters, 128B apart
__device__ unsigned g_root = 0;      // root counter (counts group completions)

__device__ __forceinline__ uint32_t packh2(float a, float b) {
    __half2 h = __floats2half2_rn(a, b);
    return *reinterpret_cast<uint32_t*>(&h);
}

__device__ __forceinline__ void mma_f16(float d[4], const uint32_t a[4], const uint32_t b[2]) {
    asm volatile(
        "mma.sync.aligned.m16n8k16.row.col.f32.f16.f16.f32 "
        "{%0,%1,%2,%3},{%4,%5,%6,%7},{%8,%9},{%0,%1,%2,%3};"
        : "+f"(d[0]), "+f"(d[1]), "+f"(d[2]), "+f"(d[3])
        : "r"(a[0]), "r"(a[1]), "r"(a[2]), "r"(a[3]), "r"(b[0]), "r"(b[1]));
}

__device__ __forceinline__ float sigm(float x) { return 1.0f / (1.0f + expf(-x)); }

// ---------------------------------------------------------------------------
// Phase 1: block tile 128x128, BK=32 (fp16), 8 warps (2m x 4n), warp 64x32.
// ---------------------------------------------------------------------------
__global__ __launch_bounds__(256) void xproj_kernel(
    const float* __restrict__ x,
    const float* __restrict__ Wf, const float* __restrict__ bf,
    const float* __restrict__ Wi, const float* __restrict__ bi,
    const float* __restrict__ Wc, const float* __restrict__ bc,
    const float* __restrict__ Wo, const float* __restrict__ bo)
{
    __shared__ uint32_t As[128][20];
    __shared__ uint32_t Bs[128][20];

    const float* Wsel[4] = {Wf, Wi, Wc, Wo};
    const float* bsel[4] = {bf, bi, bc, bo};

    const int tid  = threadIdx.x;
    const int warp = tid >> 5;
    const int lane = tid & 31;
    const int q = lane >> 2, p = lane & 3;
    const int wm = warp >> 2;
    const int wn = warp & 3;
    const int gate = blockIdx.x >> 3;
    const int r0 = (blockIdx.x & 7) * 128;
    const int m0 = blockIdx.y * 128;
    const float* __restrict__ Wg = Wsel[gate];
    const float* __restrict__ bg = bsel[gate];

    const int arow[4] = { tid >> 3, (tid+256) >> 3, (tid+512) >> 3, (tid+768) >> 3 };
    const int ac4 = (tid & 7) * 4;
    const int acu = (tid & 7) * 2;

    float acc[4][4][4];
    #pragma unroll
    for (int mt = 0; mt < 4; ++mt)
        #pragma unroll
        for (int nt = 0; nt < 4; ++nt)
            #pragma unroll
            for (int r = 0; r < 4; ++r) acc[mt][nt][r] = 0.0f;

    float4 ar[4], br[4];

    #pragma unroll
    for (int it = 0; it < 4; ++it) {
        ar[it] = *reinterpret_cast<const float4*>(&x[(size_t)(m0 + arow[it]) * 1024 + ac4]);
        br[it] = *reinterpret_cast<const float4*>(&Wg[(size_t)(r0 + arow[it]) * 2048 + 1024 + ac4]);
    }
    #pragma unroll
    for (int it = 0; it < 4; ++it) {
        uint32_t* wa = &As[arow[it]][acu];
        wa[0] = packh2(ar[it].x, ar[it].y); wa[1] = packh2(ar[it].z, ar[it].w);
        uint32_t* wb = &Bs[arow[it]][acu];
        wb[0] = packh2(br[it].x, br[it].y); wb[1] = packh2(br[it].z, br[it].w);
    }
    __syncthreads();

    for (int k0 = 0; k0 < 1024; k0 += 32) {
        if (k0 < 992) {
            #pragma unroll
            for (int it = 0; it < 4; ++it) {
                ar[it] = *reinterpret_cast<const float4*>(
                    &x[(size_t)(m0 + arow[it]) * 1024 + k0 + 32 + ac4]);
                br[it] = *reinterpret_cast<const float4*>(
                    &Wg[(size_t)(r0 + arow[it]) * 2048 + 1024 + k0 + 32 + ac4]);
            }
        }

        #pragma unroll
        for (int ks = 0; ks < 2; ++ks) {
            const int kk = ks * 8;
            uint32_t a[4][4];
            #pragma unroll
            for (int mt = 0; mt < 4; ++mt) {
                int rb = wm * 64 + mt * 16 + q;
                a[mt][0] = As[rb][kk + p];
                a[mt][1] = As[rb + 8][kk + p];
                a[mt][2] = As[rb][kk + p + 4];
                a[mt][3] = As[rb + 8][kk + p + 4];
            }
            #pragma unroll
            for (int nt = 0; nt < 4; ++nt) {
                uint32_t bb[2];
                int nr = wn * 32 + nt * 8 + q;
                bb[0] = Bs[nr][kk + p];
                bb[1] = Bs[nr][kk + p + 4];
                #pragma unroll
                for (int mt = 0; mt < 4; ++mt)
                    mma_f16(acc[mt][nt], a[mt], bb);
            }
        }
        __syncthreads();
        if (k0 < 992) {
            #pragma unroll
            for (int it = 0; it < 4; ++it) {
                uint32_t* wa = &As[arow[it]][acu];
                wa[0] = packh2(ar[it].x, ar[it].y); wa[1] = packh2(ar[it].z, ar[it].w);
                uint32_t* wb = &Bs[arow[it]][acu];
                wb[0] = packh2(br[it].x, br[it].y); wb[1] = packh2(br[it].z, br[it].w);
            }
            __syncthreads();
        }
    }

    #pragma unroll
    for (int mt = 0; mt < 4; ++mt)
        #pragma unroll
        for (int nt = 0; nt < 4; ++nt)
            #pragma unroll
            for (int r = 0; r < 4; ++r) {
                int row = wm * 64 + mt * 16 + q + ((r >> 1) << 3);
                int col = wn * 32 + nt * 8 + 2 * p + (r & 1);
                int m = m0 + row;
                int b = m >> 8;
                int s = m & 255;
                g_Xp[((size_t)(s * 128 + b) * 4096) + gate * 1024 + r0 + col] =
                    acc[mt][nt][r] + bg[r0 + col];
            }
}

// ---------------------------------------------------------------------------
// Phase 2
// ---------------------------------------------------------------------------
// Two-level grid barrier: 8 group counters (16 CTAs each) feed one root.
// Generation-based, monotone (no reset) -> deterministic across graph replays.
__device__ __forceinline__ void grid_barrier_2l() {
    __threadfence();
    __syncthreads();
    if (threadIdx.x == 0) {
        unsigned g = blockIdx.x & 7;
        unsigned old = atomicAdd(&g_grp[g * 32], 1u);
        unsigned gen = old >> 4;                 // 16 CTAs per group
        if ((old & 15u) == 15u)                  // group complete -> arrive at root
            atomicAdd(&g_root, 1u);
        unsigned target = (gen + 1u) * 8u;       // all 8 groups done this round
        while (*(volatile unsigned*)&g_root < target) {
            __nanosleep(32);
        }
        __threadfence();
    }
    __syncthreads();
}

__global__ void __launch_bounds__(256, 1) lstm_scan_kernel(
    const float* __restrict__ Wf, const float* __restrict__ Wi,
    const float* __restrict__ Wc, const float* __restrict__ Wo,
    float* __restrict__ out)
{
    extern __shared__ uint8_t smem[];
    uint32_t* Ws  = reinterpret_cast<uint32_t*>(smem);                   // [32][WS2_STRIDE]
    uint32_t* Stg = reinterpret_cast<uint32_t*>(smem) + 32 * WS2_STRIDE; // [4][3][32][AS2_STRIDE]
    float*    red = reinterpret_cast<float*>(smem) + RED_OFF;            // [128][33]

    const float* Wsel[4] = {Wf, Wi, Wc, Wo};
    const int tid  = threadIdx.x;
    const int warp = tid >> 5;
    const int lane = tid & 31;
    const int q = lane >> 2, p = lane & 3;
    const int mg = warp & 3;     // pair id (32 batches)
    const int km = warp >> 2;    // member in pair (k-interleave)
    const int j0 = blockIdx.x * 8;

    uint32_t* slab = Stg + mg * PAIR_SLAB;
    const uint32_t slab_base = (uint32_t)__cvta_generic_to_shared(slab);

    // Load Wh slice as fp16 pairs
    for (int idx = tid; idx < 32 * 256; idx += 256) {
        int cc = idx >> 8;
        int k4 = (idx & 255) * 4;
        int g = cc >> 3, jj = cc & 7;
        const float* Wg = Wsel[g];
        float4 v = *reinterpret_cast<const float4*>(&Wg[(size_t)(j0 + jj) * 2048 + k4]);
        uint32_t* wr = &Ws[cc * WS2_STRIDE + (k4 >> 1)];
        wr[0] = packh2(v.x, v.y);
        wr[1] = packh2(v.z, v.w);
    }
    for (int idx = tid; idx < 1024; idx += 256) {
        int b = idx >> 3, jj = idx & 7;
        g_h[b * 1024 + j0 + jj] = __float2half_rn(0.0f);
    }
    float cst[8];
    #pragma unroll
    for (int i = 0; i < 8; ++i) cst[i] = 0.0f;

    const int tid64 = km * 32 + lane;
    int srow[8], sc4[8];
    #pragma unroll
    for (int it = 0; it < 8; ++it) {
        int idx = tid64 + 64 * it;
        srow[it] = idx >> 4;
        sc4[it]  = (idx & 15) * 4;
    }

    grid_barrier_2l();

    for (int t = 0; t < 256; ++t) {
        const uint32_t* __restrict__ hin =
            reinterpret_cast<const uint32_t*>(&g_h[(t & 1) * (128 * 1024)]);
        __half* __restrict__ hout = &g_h[((t + 1) & 1) * (128 * 1024)];
        const uint32_t* __restrict__ hrow0 = hin + (size_t)(mg * 32) * 512;

        // prefetch Xp (km==0 epilogue owners) — hidden under chunk loop
        float2 xp[4][4];
        if (km == 0) {
            #pragma unroll
            for (int rr = 0; rr < 4; ++rr) {
                int row = mg * 32 + q + rr * 8;
                size_t base = ((size_t)(t * 128 + row)) * 4096 + j0 + 2 * p;
                #pragma unroll
                for (int g = 0; g < 4; ++g)
                    xp[rr][g] = __ldg(reinterpret_cast<const float2*>(&g_Xp[base + g * 1024]));
            }
        }

        float acc[2][4][4];
        #pragma unroll
        for (int mt = 0; mt < 2; ++mt)
            #pragma unroll
            for (int nt = 0; nt < 4; ++nt)
                #pragma unroll
                for (int r = 0; r < 4; ++r) acc[mt][nt][r] = 0.0f;

        // prologue: stage chunks 0,1 into bufs 0,1 (pair-private)
        #pragma unroll
        for (int pc = 0; pc < 2; ++pc) {
            uint32_t boff = (uint32_t)(pc * 32 * AS2_STRIDE) << 2;
            #pragma unroll
            for (int it = 0; it < 8; ++it) {
                uint32_t dsm = slab_base + boff + ((srow[it] * AS2_STRIDE + sc4[it]) << 2);
                const uint32_t* src = hrow0 + srow[it] * 512 + pc * 64 + sc4[it];
                asm volatile("cp.async.cg.shared.global [%0], [%1], 16;" :: "r"(dsm), "l"(src));
            }
            asm volatile("cp.async.commit_group;");
        }

        #pragma unroll
        for (int c = 0; c < 8; ++c) {
            if (c < 7) { asm volatile("cp.async.wait_group 1;"); }
            else       { asm volatile("cp.async.wait_group 0;"); }
            asm volatile("bar.sync %0, 64;" :: "r"(1 + mg) : "memory");

            if (c < 6) {
                uint32_t boff = (uint32_t)(((c + 2) % 3) * 32 * AS2_STRIDE) << 2;
                #pragma unroll
                for (int it = 0; it < 8; ++it) {
                    uint32_t dsm = slab_base + boff + ((srow[it] * AS2_STRIDE + sc4[it]) << 2);
                    const uint32_t* src = hrow0 + srow[it] * 512 + (c + 2) * 64 + sc4[it];
                    asm volatile("cp.async.cg.shared.global [%0], [%1], 16;" :: "r"(dsm), "l"(src));
                }
                asm volatile("cp.async.commit_group;");
            }

            const uint32_t* Ab = slab + (c % 3) * (32 * AS2_STRIDE);
            #pragma unroll
            for (int s = 0; s < 4; ++s) {
                const int fi = 2 * s + km;
                const int au = fi * 8 + p;
                const int bu = c * 64 + fi * 8 + p;
                uint32_t a[2][4];
                #pragma unroll
                for (int mt = 0; mt < 2; ++mt) {
                    int rb = mt * 16 + q;
                    a[mt][0] = Ab[rb * AS2_STRIDE + au];
                    a[mt][1] = Ab[(rb + 8) * AS2_STRIDE + au];
                    a[mt][2] = Ab[rb * AS2_STRIDE + au + 4];
                    a[mt][3] = Ab[(rb + 8) * AS2_STRIDE + au + 4];
                }
                #pragma unroll
                for (int nt = 0; nt < 4; ++nt) {
                    uint32_t bb[2];
                    int nr = nt * 8 + q;
                    bb[0] = Ws[nr * WS2_STRIDE + bu];
                    bb[1] = Ws[nr * WS2_STRIDE + bu + 4];
                    mma_f16(acc[0][nt], a[0], bb);
                    mma_f16(acc[1][nt], a[1], bb);
                }
            }
        }

        // 2-way k reduction through dedicated smem
        if (km == 1) {
            float* w = &red[(mg * 32 + lane) * 33];
            #pragma unroll
            for (int mt = 0; mt < 2; ++mt)
                #pragma unroll
                for (int nt = 0; nt < 4; ++nt)
                    #pragma unroll
                    for (int r = 0; r < 4; ++r)
                        w[mt * 16 + nt * 4 + r] = acc[mt][nt][r];
        }
        asm volatile("bar.sync %0, 64;" :: "r"(1 + mg) : "memory");
        if (km == 0) {
            const float* w = &red[(mg * 32 + lane) * 33];
            #pragma unroll
            for (int mt = 0; mt < 2; ++mt)
                #pragma unroll
                for (int nt = 0; nt < 4; ++nt)
                    #pragma unroll
                    for (int r = 0; r < 4; ++r)
                        acc[mt][nt][r] += w[mt * 16 + nt * 4 + r];

            // epilogue with packed half2 / float2 stores (jj = 2p, 2p+1 adjacent)
            #pragma unroll
            for (int mt = 0; mt < 2; ++mt)
                #pragma unroll
                for (int rh = 0; rh < 2; ++rh) {
                    int rr = mt * 2 + rh;
                    int row = mg * 32 + q + rr * 8;
                    float hv[2];
                    #pragma unroll
                    for (int e = 0; e < 2; ++e) {
                        int r = rh * 2 + e;
                        float xf = e ? xp[rr][0].y : xp[rr][0].x;
                        float xi = e ? xp[rr][1].y : xp[rr][1].x;
                        float xg = e ? xp[rr][2].y : xp[rr][2].x;
                        float xo = e ? xp[rr][3].y : xp[rr][3].x;
                        float fg = sigm(acc[mt][0][r] + xf);
                        float ig = sigm(acc[mt][1][r] + xi);
                        float gg = tanhf(acc[mt][2][r] + xg);
                        float og = sigm(acc[mt][3][r] + xo);
                        float cnew = cst[mt * 4 + r] * fg + ig * gg;
                        cst[mt * 4 + r] = cnew;
                        hv[e] = tanhf(cnew) * og;
                    }
                    *reinterpret_cast<uint32_t*>(&hout[row * 1024 + j0 + 2 * p]) =
                        packh2(hv[0], hv[1]);
                    float2 o2; o2.x = hv[0]; o2.y = hv[1];
                    *reinterpret_cast<float2*>(
                        &out[(size_t)row * (256 * 1024) + t * 1024 + j0 + 2 * p]) = o2;
                }
        }
        grid_barrier_2l();
    }
}

// ---------------------------------------------------------------------------
extern "C" void kernel_launch(void* const* d_in, const int* in_sizes, int n_in,
                              void* d_out, int out_size) {
    const float* x  = (const float*)d_in[0];
    const float* Wf = (const float*)d_in[1];
    const float* bf = (const float*)d_in[2];
    const float* Wi = (const float*)d_in[3];
    const float* bi = (const float*)d_in[4];
    const float* Wc = (const float*)d_in[5];
    const float* bc = (const float*)d_in[6];
    const float* Wo = (const float*)d_in[7];
    const float* bo = (const float*)d_in[8];
    float* out = (float*)d_out;

    cudaFuncSetAttribute(lstm_scan_kernel,
                         cudaFuncAttributeMaxDynamicSharedMemorySize, SMEM2_BYTES);

    dim3 g1(4096 / 128, 32768 / 128);
    xproj_kernel<<<g1, 256>>>(x, Wf, bf, Wi, bi, Wc, bc, Wo, bo);
    lstm_scan_kernel<<<NBLK2, 256, SMEM2_BYTES>>>(Wf, Wi, Wc, Wo, out);
}